// round 1
// baseline (speedup 1.0000x reference)
#include <cuda_runtime.h>

#define N_NODES 50000
#define N_EDGES 800000
#define R_REL 8
#define H_DIM 128
#define ROW_TILES ((N_NODES + 127) / 128)

// ---------------- scratch (device globals: allocation-free) ----------------
__device__ float g_xW[(size_t)R_REL * N_NODES * H_DIM];   // 204.8 MB
__device__ float g_h1[(size_t)N_NODES * H_DIM];
__device__ float g_h2[(size_t)N_NODES * H_DIM];
__device__ float g_sq[R_REL * N_NODES];
__device__ float g_sk[R_REL * N_NODES];
__device__ float g_wq[R_REL * H_DIM];
__device__ float g_wk[R_REL * H_DIM];
__device__ int   g_cnt[N_NODES];
__device__ int   g_rowptr[N_NODES + 1];
__device__ int   g_cursor[N_NODES];
__device__ int   g_csr[N_EDGES];

// ---------------- CSR build ----------------
__global__ void k_zero_cnt() {
    int i = blockIdx.x * blockDim.x + threadIdx.x;
    if (i < N_NODES) g_cnt[i] = 0;
}

__global__ void k_hist(const int* __restrict__ tgt) {
    int e = blockIdx.x * blockDim.x + threadIdx.x;
    if (e < N_EDGES) atomicAdd(&g_cnt[tgt[e]], 1);
}

__global__ void k_scan() {
    __shared__ int sm[1024];
    __shared__ int carry;
    int tid = threadIdx.x;
    if (tid == 0) carry = 0;
    __syncthreads();
    for (int base = 0; base < N_NODES; base += 1024) {
        int idx = base + tid;
        int v = (idx < N_NODES) ? g_cnt[idx] : 0;
        sm[tid] = v;
        __syncthreads();
        for (int off = 1; off < 1024; off <<= 1) {
            int t = (tid >= off) ? sm[tid - off] : 0;
            __syncthreads();
            sm[tid] += t;
            __syncthreads();
        }
        int excl = sm[tid] - v + carry;
        if (idx < N_NODES) { g_rowptr[idx] = excl; g_cursor[idx] = excl; }
        __syncthreads();
        if (tid == 1023) carry += sm[1023];
        __syncthreads();
    }
    if (tid == 0) g_rowptr[N_NODES] = carry;
}

__global__ void k_scatter(const int* __restrict__ src, const int* __restrict__ tgt,
                          const int* __restrict__ et) {
    int e = blockIdx.x * blockDim.x + threadIdx.x;
    if (e < N_EDGES) {
        int pos = atomicAdd(&g_cursor[tgt[e]], 1);
        g_csr[pos] = (et[e] << 17) | src[e];   // src < 2^17, etype < 8
    }
}

// ---------------- fold q/k into W:  wq[r,i] = W[r,i,:]·q ----------------
__global__ void k_wqk(const float* __restrict__ W, const float* __restrict__ q,
                      const float* __restrict__ kv) {
    int idx = blockIdx.x * blockDim.x + threadIdx.x;   // r*H + i
    if (idx >= R_REL * H_DIM) return;
    const float* w = W + (size_t)idx * H_DIM;
    float aq = 0.f, ak = 0.f;
#pragma unroll 4
    for (int h = 0; h < H_DIM; h++) { float wv = w[h]; aq += wv * q[h]; ak += wv * kv[h]; }
    g_wq[idx] = aq; g_wk[idx] = ak;
}

// ---------------- s_q[r,n] = act[n]·wq[r],  s_k[r,n] = act[n]·wk[r] ----------------
__global__ __launch_bounds__(256) void k_sqk(const float* __restrict__ actp, int aSel) {
    __shared__ float swq[R_REL * H_DIM], swk[R_REL * H_DIM];
    const float* act = (aSel == 0) ? actp : (aSel == 1 ? g_h1 : g_h2);
    int tid = threadIdx.x;
    for (int i = tid; i < R_REL * H_DIM; i += blockDim.x) { swq[i] = g_wq[i]; swk[i] = g_wk[i]; }
    __syncthreads();
    int n = blockIdx.x * 8 + (tid >> 5);
    int lane = tid & 31;
    if (n >= N_NODES) return;
    float4 a = *(const float4*)&act[(size_t)n * H_DIM + lane * 4];
    float accq[R_REL], acck[R_REL];
#pragma unroll
    for (int r = 0; r < R_REL; r++) {
        float4 wq4 = *(const float4*)&swq[r * H_DIM + lane * 4];
        float4 wk4 = *(const float4*)&swk[r * H_DIM + lane * 4];
        accq[r] = a.x * wq4.x + a.y * wq4.y + a.z * wq4.z + a.w * wq4.w;
        acck[r] = a.x * wk4.x + a.y * wk4.y + a.z * wk4.z + a.w * wk4.w;
    }
#pragma unroll
    for (int off = 16; off > 0; off >>= 1)
#pragma unroll
        for (int r = 0; r < R_REL; r++) {
            accq[r] += __shfl_xor_sync(0xffffffffu, accq[r], off);
            acck[r] += __shfl_xor_sync(0xffffffffu, acck[r], off);
        }
    if (lane < R_REL)            g_sq[lane * N_NODES + n] = accq[lane];
    else if (lane < 2 * R_REL)   g_sk[(lane - R_REL) * N_NODES + n] = acck[lane - R_REL];
}

// ---------------- fp32 GEMM with packed f32x2 FFMA2 ----------------
__device__ __forceinline__ void ffma2(unsigned long long& d, unsigned long long a,
                                      unsigned long long b) {
    asm volatile("fma.rn.f32x2 %0, %1, %2, %0;" : "+l"(d) : "l"(a), "l"(b));
}
__device__ __forceinline__ unsigned long long bc2(float x) {
    unsigned long long r;
    unsigned int u = __float_as_uint(x);
    asm("mov.b64 %0, {%1, %1};" : "=l"(r) : "r"(u));
    return r;
}

// C[row,col] = sum_k A[row,k] * (TRANSB ? B[col,k] : B[k,col]) (+bias)
// blockIdx.y selects relation slice: B += y*strideB, C += y*strideC.
template<bool TRANSB, bool BIAS>
__global__ __launch_bounds__(256) void k_gemm(
    const float* __restrict__ Ap, int aSel,
    const float* __restrict__ B,
    float* __restrict__ Cp, int cSel,
    const float* __restrict__ bias,
    int M, long strideB, long strideC)
{
    __shared__ float As[32][132];
    __shared__ float Bs[32][132];
    const float* A = (aSel == 0) ? Ap : (aSel == 1 ? g_h1 : g_h2);
    float* C = (cSel == 0) ? Cp : g_xW;
    int tid = threadIdx.x;
    int tx = tid & 15, ty = tid >> 4;
    int rowBase = blockIdx.x * 128;
    const float* Bp = B + (size_t)blockIdx.y * strideB;
    float* Cb = C + (size_t)blockIdx.y * strideC;

    unsigned long long acc2[4][8];
#pragma unroll
    for (int i = 0; i < 4; i++)
#pragma unroll
        for (int j = 0; j < 8; j++) acc2[i][j] = 0ull;

    for (int k0 = 0; k0 < 128; k0 += 32) {
#pragma unroll
        for (int it = 0; it < 4; it++) {
            int f = it * 256 + tid;
            int row = f >> 3, kq = f & 7;
            float4 v = make_float4(0.f, 0.f, 0.f, 0.f);
            if (rowBase + row < M)
                v = *(const float4*)&A[(size_t)(rowBase + row) * 128 + k0 + kq * 4];
            As[kq * 4 + 0][row] = v.x;
            As[kq * 4 + 1][row] = v.y;
            As[kq * 4 + 2][row] = v.z;
            As[kq * 4 + 3][row] = v.w;
        }
        if (!TRANSB) {
#pragma unroll
            for (int it = 0; it < 4; it++) {
                int f = it * 256 + tid;
                int kk = f >> 5, colq = f & 31;
                float4 v = *(const float4*)&Bp[(size_t)(k0 + kk) * 128 + colq * 4];
                *(float4*)&Bs[kk][colq * 4] = v;
            }
        } else {
#pragma unroll
            for (int it = 0; it < 4; it++) {
                int f = it * 256 + tid;
                int col = f >> 3, kq = f & 7;
                float4 v = *(const float4*)&Bp[(size_t)col * 128 + k0 + kq * 4];
                Bs[kq * 4 + 0][col] = v.x;
                Bs[kq * 4 + 1][col] = v.y;
                Bs[kq * 4 + 2][col] = v.z;
                Bs[kq * 4 + 3][col] = v.w;
            }
        }
        __syncthreads();
#pragma unroll 4
        for (int kk = 0; kk < 32; kk++) {
            const unsigned long long* ap = (const unsigned long long*)&As[kk][ty * 8];
            unsigned long long a0 = ap[0], a1 = ap[1], a2 = ap[2], a3 = ap[3];
            float4 bA = *(const float4*)&Bs[kk][tx * 8];
            float4 bB = *(const float4*)&Bs[kk][tx * 8 + 4];
            unsigned long long bb[8];
            bb[0] = bc2(bA.x); bb[1] = bc2(bA.y); bb[2] = bc2(bA.z); bb[3] = bc2(bA.w);
            bb[4] = bc2(bB.x); bb[5] = bc2(bB.y); bb[6] = bc2(bB.z); bb[7] = bc2(bB.w);
#pragma unroll
            for (int j = 0; j < 8; j++) {
                ffma2(acc2[0][j], a0, bb[j]);
                ffma2(acc2[1][j], a1, bb[j]);
                ffma2(acc2[2][j], a2, bb[j]);
                ffma2(acc2[3][j], a3, bb[j]);
            }
        }
        __syncthreads();
    }
#pragma unroll
    for (int i4 = 0; i4 < 4; i4++) {
        int row0 = rowBase + ty * 8 + 2 * i4;
#pragma unroll
        for (int half = 0; half < 2; half++) {
            int row = row0 + half;
            if (row >= M) continue;
            float o[8];
#pragma unroll
            for (int j = 0; j < 8; j++) {
                float2 p = *(float2*)&acc2[i4][j];
                o[j] = half ? p.y : p.x;
            }
            if (BIAS) {
#pragma unroll
                for (int j = 0; j < 8; j++) o[j] += bias[tx * 8 + j];
            }
            *(float4*)&Cb[(size_t)row * 128 + tx * 8]     = make_float4(o[0], o[1], o[2], o[3]);
            *(float4*)&Cb[(size_t)row * 128 + tx * 8 + 4] = make_float4(o[4], o[5], o[6], o[7]);
        }
    }
}

// ---------------- softmax + aggregate (warp per target node, CSR) ----------------
__global__ __launch_bounds__(256) void k_agg(const float* __restrict__ bias, int outSel) {
    int tid = threadIdx.x;
    int lane = tid & 31;
    int n = blockIdx.x * 8 + (tid >> 5);
    if (n >= N_NODES) return;
    float* out = (outSel == 1) ? g_h1 : g_h2;
    int s = g_rowptr[n], e = g_rowptr[n + 1];

    float mx = -3.0e38f;
    for (int i = s + lane; i < e; i += 32) {
        int p = g_csr[i]; int sr = p & 0x1FFFF; int r = p >> 17;
        float v = g_sq[r * N_NODES + n] + g_sk[r * N_NODES + sr];
        v = v > 0.f ? v : 0.2f * v;
        mx = fmaxf(mx, v);
    }
#pragma unroll
    for (int off = 16; off > 0; off >>= 1) mx = fmaxf(mx, __shfl_xor_sync(0xffffffffu, mx, off));

    float den = 0.f;
    for (int i = s + lane; i < e; i += 32) {
        int p = g_csr[i]; int sr = p & 0x1FFFF; int r = p >> 17;
        float v = g_sq[r * N_NODES + n] + g_sk[r * N_NODES + sr];
        v = v > 0.f ? v : 0.2f * v;
        den += __expf(v - mx);
    }
#pragma unroll
    for (int off = 16; off > 0; off >>= 1) den += __shfl_xor_sync(0xffffffffu, den, off);
    float inv = 1.f / (den + 1e-16f);

    float4 acc = make_float4(0.f, 0.f, 0.f, 0.f);
    int i = s;
    for (; i + 1 < e; i += 2) {
        int p0 = g_csr[i], p1 = g_csr[i + 1];
        int s0 = p0 & 0x1FFFF, r0 = p0 >> 17;
        int s1 = p1 & 0x1FFFF, r1 = p1 >> 17;
        float v0 = g_sq[r0 * N_NODES + n] + g_sk[r0 * N_NODES + s0];
        float v1 = g_sq[r1 * N_NODES + n] + g_sk[r1 * N_NODES + s1];
        v0 = v0 > 0.f ? v0 : 0.2f * v0;
        v1 = v1 > 0.f ? v1 : 0.2f * v1;
        float w0 = __expf(v0 - mx) * inv;
        float w1 = __expf(v1 - mx) * inv;
        float4 ra = *(const float4*)&g_xW[((size_t)r0 * N_NODES + s0) * 128 + lane * 4];
        float4 rb = *(const float4*)&g_xW[((size_t)r1 * N_NODES + s1) * 128 + lane * 4];
        acc.x += w0 * ra.x + w1 * rb.x;
        acc.y += w0 * ra.y + w1 * rb.y;
        acc.z += w0 * ra.z + w1 * rb.z;
        acc.w += w0 * ra.w + w1 * rb.w;
    }
    if (i < e) {
        int p = g_csr[i]; int s0 = p & 0x1FFFF; int r = p >> 17;
        float v = g_sq[r * N_NODES + n] + g_sk[r * N_NODES + s0];
        v = v > 0.f ? v : 0.2f * v;
        float w = __expf(v - mx) * inv;
        float4 ra = *(const float4*)&g_xW[((size_t)r * N_NODES + s0) * 128 + lane * 4];
        acc.x += w * ra.x; acc.y += w * ra.y; acc.z += w * ra.z; acc.w += w * ra.w;
    }
    float4 bv = *(const float4*)&bias[lane * 4];
    float4 o;
    o.x = fmaxf(acc.x + bv.x, 0.f);
    o.y = fmaxf(acc.y + bv.y, 0.f);
    o.z = fmaxf(acc.z + bv.z, 0.f);
    o.w = fmaxf(acc.w + bv.w, 0.f);
    *(float4*)&out[(size_t)n * 128 + lane * 4] = o;
}

// ---------------- launch ----------------
extern "C" void kernel_launch(void* const* d_in, const int* in_sizes, int n_in,
                              void* d_out, int out_size) {
    const float* x  = (const float*)d_in[0];
    const int*   ei = (const int*)d_in[1];
    const int*   et = (const int*)d_in[2];
    const float* W1 = (const float*)d_in[4];
    const float* q1 = (const float*)d_in[5];
    const float* k1 = (const float*)d_in[6];
    const float* b1 = (const float*)d_in[7];
    const float* W2 = (const float*)d_in[8];
    const float* q2 = (const float*)d_in[9];
    const float* k2 = (const float*)d_in[10];
    const float* b2 = (const float*)d_in[11];
    const float* Wl = (const float*)d_in[12];
    const float* bl = (const float*)d_in[13];
    float* out = (float*)d_out;
    const int* srcp = ei;
    const int* tgtp = ei + N_EDGES;

    // CSR build (deterministic up to intra-segment order; sums within fp tolerance)
    k_zero_cnt<<<(N_NODES + 255) / 256, 256>>>();
    k_hist<<<(N_EDGES + 255) / 256, 256>>>(tgtp);
    k_scan<<<1, 1024>>>();
    k_scatter<<<(N_EDGES + 255) / 256, 256>>>(srcp, tgtp, et);

    dim3 gRel(ROW_TILES, R_REL);
    dim3 gWarp((N_NODES + 7) / 8);

    // layer 1
    k_gemm<false, false><<<gRel, 256>>>(x, 0, W1, nullptr, 1, nullptr,
                                        N_NODES, (long)128 * 128, (long)N_NODES * 128);
    k_wqk<<<4, 256>>>(W1, q1, k1);
    k_sqk<<<gWarp, 256>>>(x, 0);
    k_agg<<<gWarp, 256>>>(b1, 1);

    // layer 2
    k_gemm<false, false><<<gRel, 256>>>(nullptr, 1, W2, nullptr, 1, nullptr,
                                        N_NODES, (long)128 * 128, (long)N_NODES * 128);
    k_wqk<<<4, 256>>>(W2, q2, k2);
    k_sqk<<<gWarp, 256>>>(nullptr, 1);
    k_agg<<<gWarp, 256>>>(b2, 2);

    // final linear: out = h2 @ Wl^T + bl  ([B,NPG,H] is contiguous [N,H])
    k_gemm<true, true><<<dim3(ROW_TILES, 1), 256>>>(nullptr, 2, Wl, out, 0, bl,
                                                    N_NODES, 0L, 0L);
}

// round 4
// speedup vs baseline: 1.5384x; 1.5384x over previous
#include <cuda_runtime.h>
#include <cuda_bf16.h>
#include <cstdint>

#define N_NODES 50000
#define N_EDGES 800000
#define R_REL 8
#define H_DIM 128
#define ROW_TILES ((N_NODES + 127) / 128)

// ---------------- scratch (device globals: allocation-free) ----------------
__device__ float g_xW[(size_t)R_REL * N_NODES * H_DIM];   // 204.8 MB
__device__ float g_h1[(size_t)N_NODES * H_DIM];
__device__ float g_h2[(size_t)N_NODES * H_DIM];
__device__ float g_sq[R_REL * N_NODES];
__device__ float g_sk[R_REL * N_NODES];
__device__ float g_wq[R_REL * H_DIM];
__device__ float g_wk[R_REL * H_DIM];
__device__ int   g_cnt[N_NODES];
__device__ int   g_rowptr[N_NODES + 1];
__device__ int   g_cursor[N_NODES];
__device__ int   g_csr[N_EDGES];
// split-bf16 operands for tensor-core GEMM
__device__ __nv_bfloat16 g_ahi[(size_t)N_NODES * H_DIM];
__device__ __nv_bfloat16 g_alo[(size_t)N_NODES * H_DIM];
__device__ __nv_bfloat16 g_bhi[R_REL * H_DIM * H_DIM];    // [r][n][k] = W[r][k][n]
__device__ __nv_bfloat16 g_blo[R_REL * H_DIM * H_DIM];

__device__ __forceinline__ uint32_t smem_u32(const void* p) {
    uint32_t a;
    asm("{ .reg .u64 t; cvta.to.shared.u64 t, %1; cvt.u32.u64 %0, t; }" : "=r"(a) : "l"(p));
    return a;
}

// ---------------- CSR build ----------------
__global__ void k_zero_cnt() {
    int i = blockIdx.x * blockDim.x + threadIdx.x;
    if (i < N_NODES) g_cnt[i] = 0;
}
__global__ void k_hist(const int* __restrict__ tgt) {
    int e = blockIdx.x * blockDim.x + threadIdx.x;
    if (e < N_EDGES) atomicAdd(&g_cnt[tgt[e]], 1);
}
__global__ void k_scan() {
    __shared__ int sm[1024];
    __shared__ int carry;
    int tid = threadIdx.x;
    if (tid == 0) carry = 0;
    __syncthreads();
    for (int base = 0; base < N_NODES; base += 1024) {
        int idx = base + tid;
        int v = (idx < N_NODES) ? g_cnt[idx] : 0;
        sm[tid] = v;
        __syncthreads();
        for (int off = 1; off < 1024; off <<= 1) {
            int t = (tid >= off) ? sm[tid - off] : 0;
            __syncthreads();
            sm[tid] += t;
            __syncthreads();
        }
        int excl = sm[tid] - v + carry;
        if (idx < N_NODES) { g_rowptr[idx] = excl; g_cursor[idx] = excl; }
        __syncthreads();
        if (tid == 1023) carry += sm[1023];
        __syncthreads();
    }
    if (tid == 0) g_rowptr[N_NODES] = carry;
}
__global__ void k_scatter(const int* __restrict__ src, const int* __restrict__ tgt,
                          const int* __restrict__ et) {
    int e = blockIdx.x * blockDim.x + threadIdx.x;
    if (e < N_EDGES) {
        int pos = atomicAdd(&g_cursor[tgt[e]], 1);
        g_csr[pos] = (et[e] << 17) | src[e];
    }
}

// ---------------- bf16 hi/lo splits ----------------
__global__ void k_split_act(const float* __restrict__ actp, int aSel, int total4) {
    const float* act = (aSel == 0) ? actp : g_h1;
    int i = blockIdx.x * blockDim.x + threadIdx.x;
    if (i >= total4) return;
    float4 v = *(const float4*)&act[i * 4];
    __nv_bfloat16 h0 = __float2bfloat16(v.x), h1 = __float2bfloat16(v.y);
    __nv_bfloat16 h2 = __float2bfloat16(v.z), h3 = __float2bfloat16(v.w);
    __nv_bfloat162* ph = (__nv_bfloat162*)&g_ahi[i * 4];
    __nv_bfloat162* pl = (__nv_bfloat162*)&g_alo[i * 4];
    ph[0] = __nv_bfloat162(h0, h1);
    ph[1] = __nv_bfloat162(h2, h3);
    pl[0] = __nv_bfloat162(__float2bfloat16(v.x - __bfloat162float(h0)),
                           __float2bfloat16(v.y - __bfloat162float(h1)));
    pl[1] = __nv_bfloat162(__float2bfloat16(v.z - __bfloat162float(h2)),
                           __float2bfloat16(v.w - __bfloat162float(h3)));
}
// B[r][n][k] = W[r][k][n], split hi/lo
__global__ void k_split_W(const float* __restrict__ W) {
    int i = blockIdx.x * blockDim.x + threadIdx.x;   // r*16384 + n*128 + k
    if (i >= R_REL * H_DIM * H_DIM) return;
    int k = i & 127, n = (i >> 7) & 127, r = i >> 14;
    float w = W[(size_t)r * 16384 + k * 128 + n];
    __nv_bfloat16 h = __float2bfloat16(w);
    g_bhi[i] = h;
    g_blo[i] = __float2bfloat16(w - __bfloat162float(h));
}

// ---------------- HMMA GEMM: g_xW[r] = act @ W[r]  (split-bf16, 3 terms) ----------------
// CTA: 128 rows x 128 cols, 8 warps (4 row x 2 col), warp tile 32x64.
__global__ __launch_bounds__(256) void k_hgemm() {
    __shared__ __nv_bfloat16 sA[128][72];   // [row][k-chunk], pad 72 for ldmatrix
    __shared__ __nv_bfloat16 sB[128][72];   // [n][k-chunk]
    int tid = threadIdx.x;
    int wid = tid >> 5, lane = tid & 31;
    int wr = wid >> 1, wc = wid & 1;
    int r = blockIdx.y;
    int rowBase = blockIdx.x * 128;

    float acc[2][8][4];
#pragma unroll
    for (int mi = 0; mi < 2; mi++)
#pragma unroll
        for (int ni = 0; ni < 8; ni++)
#pragma unroll
            for (int j = 0; j < 4; j++) acc[mi][ni][j] = 0.f;

    const __nv_bfloat16* Aseg[3] = { g_ahi, g_ahi, g_alo };
    const __nv_bfloat16* Bseg[3] = { g_bhi + (size_t)r * 16384,
                                     g_blo + (size_t)r * 16384,
                                     g_bhi + (size_t)r * 16384 };

    // ldmatrix lane-address components
    int m8  = lane >> 3;                   // which 8x8 matrix this lane addresses
    int arow = (m8 & 1) * 8 + (lane & 7);  // A: row offset within 16-row frag
    int acol = (m8 >> 1) * 8;              // A: k offset within 16-k step
    int bnr  = (m8 >> 1) * 8 + (lane & 7); // B: n offset within 16-n pair
    int bkc  = (m8 & 1) * 8;               // B: k offset
    uint32_t sAb = smem_u32(&sA[0][0]);
    uint32_t sBb = smem_u32(&sB[0][0]);

    for (int seg = 0; seg < 3; seg++) {
        const __nv_bfloat16* Ap = Aseg[seg];
        const __nv_bfloat16* Bp = Bseg[seg];
#pragma unroll 1
        for (int c = 0; c < 2; c++) {
            __syncthreads();
#pragma unroll
            for (int it = 0; it < 4; it++) {
                int f = it * 256 + tid;
                int row = f >> 3, sgm = f & 7;
                int grow = rowBase + row;
                float4 av = make_float4(0.f, 0.f, 0.f, 0.f);
                if (grow < N_NODES)
                    av = *(const float4*)&Ap[(size_t)grow * 128 + c * 64 + sgm * 8];
                *(float4*)&sA[row][sgm * 8] = av;
                float4 bv = *(const float4*)&Bp[(size_t)row * 128 + c * 64 + sgm * 8];
                *(float4*)&sB[row][sgm * 8] = bv;
            }
            __syncthreads();
#pragma unroll
            for (int ks = 0; ks < 4; ks++) {
                int kc = ks * 16;
                uint32_t a[2][4];
#pragma unroll
                for (int mi = 0; mi < 2; mi++) {
                    uint32_t addr = sAb + ((wr * 32 + mi * 16 + arow) * 72 + kc + acol) * 2;
                    asm volatile("ldmatrix.sync.aligned.m8n8.x4.shared.b16 {%0,%1,%2,%3}, [%4];"
                                 : "=r"(a[mi][0]), "=r"(a[mi][1]), "=r"(a[mi][2]), "=r"(a[mi][3])
                                 : "r"(addr));
                }
                uint32_t b[8][2];
#pragma unroll
                for (int np = 0; np < 4; np++) {   // each covers 16 n = 2 frags
                    uint32_t addr = sBb + ((wc * 64 + np * 16 + bnr) * 72 + kc + bkc) * 2;
                    asm volatile("ldmatrix.sync.aligned.m8n8.x4.shared.b16 {%0,%1,%2,%3}, [%4];"
                                 : "=r"(b[np * 2][0]), "=r"(b[np * 2][1]),
                                   "=r"(b[np * 2 + 1][0]), "=r"(b[np * 2 + 1][1])
                                 : "r"(addr));
                }
#pragma unroll
                for (int mi = 0; mi < 2; mi++)
#pragma unroll
                    for (int ni = 0; ni < 8; ni++) {
                        asm volatile(
                            "mma.sync.aligned.m16n8k16.row.col.f32.bf16.bf16.f32 "
                            "{%0,%1,%2,%3}, {%4,%5,%6,%7}, {%8,%9}, {%0,%1,%2,%3};"
                            : "+f"(acc[mi][ni][0]), "+f"(acc[mi][ni][1]),
                              "+f"(acc[mi][ni][2]), "+f"(acc[mi][ni][3])
                            : "r"(a[mi][0]), "r"(a[mi][1]), "r"(a[mi][2]), "r"(a[mi][3]),
                              "r"(b[ni][0]), "r"(b[ni][1]));
                    }
            }
        }
    }

    // epilogue: D frag layout -> g_xW[r]
    float* dst = g_xW + (size_t)r * N_NODES * 128;
    int lr = lane >> 2, lc = (lane & 3) * 2;
#pragma unroll
    for (int mi = 0; mi < 2; mi++) {
        int row0 = rowBase + wr * 32 + mi * 16 + lr;
#pragma unroll
        for (int ni = 0; ni < 8; ni++) {
            int col = wc * 64 + ni * 8 + lc;
            if (row0 < N_NODES)
                *(float2*)&dst[(size_t)row0 * 128 + col] =
                    make_float2(acc[mi][ni][0], acc[mi][ni][1]);
            if (row0 + 8 < N_NODES)
                *(float2*)&dst[(size_t)(row0 + 8) * 128 + col] =
                    make_float2(acc[mi][ni][2], acc[mi][ni][3]);
        }
    }
}

// ---------------- fold q/k into W ----------------
__global__ void k_wqk(const float* __restrict__ W, const float* __restrict__ q,
                      const float* __restrict__ kv) {
    int idx = blockIdx.x * blockDim.x + threadIdx.x;
    if (idx >= R_REL * H_DIM) return;
    const float* w = W + (size_t)idx * H_DIM;
    float aq = 0.f, ak = 0.f;
#pragma unroll 4
    for (int h = 0; h < H_DIM; h++) { float wv = w[h]; aq += wv * q[h]; ak += wv * kv[h]; }
    g_wq[idx] = aq; g_wk[idx] = ak;
}

// ---------------- s_q / s_k ----------------
__global__ __launch_bounds__(256) void k_sqk(const float* __restrict__ actp, int aSel) {
    __shared__ float swq[R_REL * H_DIM], swk[R_REL * H_DIM];
    const float* act = (aSel == 0) ? actp : (aSel == 1 ? g_h1 : g_h2);
    int tid = threadIdx.x;
    for (int i = tid; i < R_REL * H_DIM; i += blockDim.x) { swq[i] = g_wq[i]; swk[i] = g_wk[i]; }
    __syncthreads();
    int n = blockIdx.x * 8 + (tid >> 5);
    int lane = tid & 31;
    if (n >= N_NODES) return;
    float4 a = *(const float4*)&act[(size_t)n * H_DIM + lane * 4];
    float accq[R_REL], acck[R_REL];
#pragma unroll
    for (int r = 0; r < R_REL; r++) {
        float4 wq4 = *(const float4*)&swq[r * H_DIM + lane * 4];
        float4 wk4 = *(const float4*)&swk[r * H_DIM + lane * 4];
        accq[r] = a.x * wq4.x + a.y * wq4.y + a.z * wq4.z + a.w * wq4.w;
        acck[r] = a.x * wk4.x + a.y * wk4.y + a.z * wk4.z + a.w * wk4.w;
    }
#pragma unroll
    for (int off = 16; off > 0; off >>= 1)
#pragma unroll
        for (int r = 0; r < R_REL; r++) {
            accq[r] += __shfl_xor_sync(0xffffffffu, accq[r], off);
            acck[r] += __shfl_xor_sync(0xffffffffu, acck[r], off);
        }
    if (lane < R_REL)            g_sq[lane * N_NODES + n] = accq[lane];
    else if (lane < 2 * R_REL)   g_sk[(lane - R_REL) * N_NODES + n] = acck[lane - R_REL];
}

// ---------------- fp32 GEMM (final linear only) ----------------
__device__ __forceinline__ void ffma2(unsigned long long& d, unsigned long long a,
                                      unsigned long long b) {
    asm volatile("fma.rn.f32x2 %0, %1, %2, %0;" : "+l"(d) : "l"(a), "l"(b));
}
__device__ __forceinline__ unsigned long long bc2(float x) {
    unsigned long long r;
    unsigned int u = __float_as_uint(x);
    asm("mov.b64 %0, {%1, %1};" : "=l"(r) : "r"(u));
    return r;
}
template<bool TRANSB, bool BIAS>
__global__ __launch_bounds__(256) void k_gemm(
    const float* __restrict__ Ap, int aSel,
    const float* __restrict__ B,
    float* __restrict__ Cp, int cSel,
    const float* __restrict__ bias,
    int M, long strideB, long strideC)
{
    __shared__ float As[32][132];
    __shared__ float Bs[32][132];
    const float* A = (aSel == 0) ? Ap : (aSel == 1 ? g_h1 : g_h2);
    float* C = (cSel == 0) ? Cp : g_xW;
    int tid = threadIdx.x;
    int tx = tid & 15, ty = tid >> 4;
    int rowBase = blockIdx.x * 128;
    const float* Bp = B + (size_t)blockIdx.y * strideB;
    float* Cb = C + (size_t)blockIdx.y * strideC;

    unsigned long long acc2[4][8];
#pragma unroll
    for (int i = 0; i < 4; i++)
#pragma unroll
        for (int j = 0; j < 8; j++) acc2[i][j] = 0ull;

    for (int k0 = 0; k0 < 128; k0 += 32) {
#pragma unroll
        for (int it = 0; it < 4; it++) {
            int f = it * 256 + tid;
            int row = f >> 3, kq = f & 7;
            float4 v = make_float4(0.f, 0.f, 0.f, 0.f);
            if (rowBase + row < M)
                v = *(const float4*)&A[(size_t)(rowBase + row) * 128 + k0 + kq * 4];
            As[kq * 4 + 0][row] = v.x;
            As[kq * 4 + 1][row] = v.y;
            As[kq * 4 + 2][row] = v.z;
            As[kq * 4 + 3][row] = v.w;
        }
        if (!TRANSB) {
#pragma unroll
            for (int it = 0; it < 4; it++) {
                int f = it * 256 + tid;
                int kk = f >> 5, colq = f & 31;
                float4 v = *(const float4*)&Bp[(size_t)(k0 + kk) * 128 + colq * 4];
                *(float4*)&Bs[kk][colq * 4] = v;
            }
        } else {
#pragma unroll
            for (int it = 0; it < 4; it++) {
                int f = it * 256 + tid;
                int col = f >> 3, kq = f & 7;
                float4 v = *(const float4*)&Bp[(size_t)col * 128 + k0 + kq * 4];
                Bs[kq * 4 + 0][col] = v.x;
                Bs[kq * 4 + 1][col] = v.y;
                Bs[kq * 4 + 2][col] = v.z;
                Bs[kq * 4 + 3][col] = v.w;
            }
        }
        __syncthreads();
#pragma unroll 4
        for (int kk = 0; kk < 32; kk++) {
            const unsigned long long* ap = (const unsigned long long*)&As[kk][ty * 8];
            unsigned long long a0 = ap[0], a1 = ap[1], a2 = ap[2], a3 = ap[3];
            float4 bA = *(const float4*)&Bs[kk][tx * 8];
            float4 bB = *(const float4*)&Bs[kk][tx * 8 + 4];
            unsigned long long bb[8];
            bb[0] = bc2(bA.x); bb[1] = bc2(bA.y); bb[2] = bc2(bA.z); bb[3] = bc2(bA.w);
            bb[4] = bc2(bB.x); bb[5] = bc2(bB.y); bb[6] = bc2(bB.z); bb[7] = bc2(bB.w);
#pragma unroll
            for (int j = 0; j < 8; j++) {
                ffma2(acc2[0][j], a0, bb[j]);
                ffma2(acc2[1][j], a1, bb[j]);
                ffma2(acc2[2][j], a2, bb[j]);
                ffma2(acc2[3][j], a3, bb[j]);
            }
        }
        __syncthreads();
    }
#pragma unroll
    for (int i4 = 0; i4 < 4; i4++) {
        int row0 = rowBase + ty * 8 + 2 * i4;
#pragma unroll
        for (int half = 0; half < 2; half++) {
            int row = row0 + half;
            if (row >= M) continue;
            float o[8];
#pragma unroll
            for (int j = 0; j < 8; j++) {
                float2 p = *(float2*)&acc2[i4][j];
                o[j] = half ? p.y : p.x;
            }
            if (BIAS) {
#pragma unroll
                for (int j = 0; j < 8; j++) o[j] += bias[tx * 8 + j];
            }
            *(float4*)&Cb[(size_t)row * 128 + tx * 8]     = make_float4(o[0], o[1], o[2], o[3]);
            *(float4*)&Cb[(size_t)row * 128 + tx * 8 + 4] = make_float4(o[4], o[5], o[6], o[7]);
        }
    }
}

// ---------------- softmax + aggregate ----------------
__global__ __launch_bounds__(256) void k_agg(const float* __restrict__ bias, int outSel) {
    int tid = threadIdx.x;
    int lane = tid & 31;
    int n = blockIdx.x * 8 + (tid >> 5);
    if (n >= N_NODES) return;
    float* out = (outSel == 1) ? g_h1 : g_h2;
    int s = g_rowptr[n], e = g_rowptr[n + 1];

    float mx = -3.0e38f;
    for (int i = s + lane; i < e; i += 32) {
        int p = g_csr[i]; int sr = p & 0x1FFFF; int r = p >> 17;
        float v = g_sq[r * N_NODES + n] + g_sk[r * N_NODES + sr];
        v = v > 0.f ? v : 0.2f * v;
        mx = fmaxf(mx, v);
    }
#pragma unroll
    for (int off = 16; off > 0; off >>= 1) mx = fmaxf(mx, __shfl_xor_sync(0xffffffffu, mx, off));

    float den = 0.f;
    for (int i = s + lane; i < e; i += 32) {
        int p = g_csr[i]; int sr = p & 0x1FFFF; int r = p >> 17;
        float v = g_sq[r * N_NODES + n] + g_sk[r * N_NODES + sr];
        v = v > 0.f ? v : 0.2f * v;
        den += __expf(v - mx);
    }
#pragma unroll
    for (int off = 16; off > 0; off >>= 1) den += __shfl_xor_sync(0xffffffffu, den, off);
    float inv = 1.f / (den + 1e-16f);

    float4 acc = make_float4(0.f, 0.f, 0.f, 0.f);
    int i = s;
    for (; i + 1 < e; i += 2) {
        int p0 = g_csr[i], p1 = g_csr[i + 1];
        int s0 = p0 & 0x1FFFF, r0 = p0 >> 17;
        int s1 = p1 & 0x1FFFF, r1 = p1 >> 17;
        float v0 = g_sq[r0 * N_NODES + n] + g_sk[r0 * N_NODES + s0];
        float v1 = g_sq[r1 * N_NODES + n] + g_sk[r1 * N_NODES + s1];
        v0 = v0 > 0.f ? v0 : 0.2f * v0;
        v1 = v1 > 0.f ? v1 : 0.2f * v1;
        float w0 = __expf(v0 - mx) * inv;
        float w1 = __expf(v1 - mx) * inv;
        float4 ra = *(const float4*)&g_xW[((size_t)r0 * N_NODES + s0) * 128 + lane * 4];
        float4 rb = *(const float4*)&g_xW[((size_t)r1 * N_NODES + s1) * 128 + lane * 4];
        acc.x += w0 * ra.x + w1 * rb.x;
        acc.y += w0 * ra.y + w1 * rb.y;
        acc.z += w0 * ra.z + w1 * rb.z;
        acc.w += w0 * ra.w + w1 * rb.w;
    }
    if (i < e) {
        int p = g_csr[i]; int s0 = p & 0x1FFFF; int r = p >> 17;
        float v = g_sq[r * N_NODES + n] + g_sk[r * N_NODES + s0];
        v = v > 0.f ? v : 0.2f * v;
        float w = __expf(v - mx) * inv;
        float4 ra = *(const float4*)&g_xW[((size_t)r * N_NODES + s0) * 128 + lane * 4];
        acc.x += w * ra.x; acc.y += w * ra.y; acc.z += w * ra.z; acc.w += w * ra.w;
    }
    float4 bv = *(const float4*)&bias[lane * 4];
    float4 o;
    o.x = fmaxf(acc.x + bv.x, 0.f);
    o.y = fmaxf(acc.y + bv.y, 0.f);
    o.z = fmaxf(acc.z + bv.z, 0.f);
    o.w = fmaxf(acc.w + bv.w, 0.f);
    *(float4*)&out[(size_t)n * 128 + lane * 4] = o;
}

// ---------------- launch ----------------
extern "C" void kernel_launch(void* const* d_in, const int* in_sizes, int n_in,
                              void* d_out, int out_size) {
    const float* x  = (const float*)d_in[0];
    const int*   ei = (const int*)d_in[1];
    const int*   et = (const int*)d_in[2];
    const float* W1 = (const float*)d_in[4];
    const float* q1 = (const float*)d_in[5];
    const float* k1 = (const float*)d_in[6];
    const float* b1 = (const float*)d_in[7];
    const float* W2 = (const float*)d_in[8];
    const float* q2 = (const float*)d_in[9];
    const float* k2 = (const float*)d_in[10];
    const float* b2 = (const float*)d_in[11];
    const float* Wl = (const float*)d_in[12];
    const float* bl = (const float*)d_in[13];
    float* out = (float*)d_out;
    const int* srcp = ei;
    const int* tgtp = ei + N_EDGES;

    // CSR build
    k_zero_cnt<<<(N_NODES + 255) / 256, 256>>>();
    k_hist<<<(N_EDGES + 255) / 256, 256>>>(tgtp);
    k_scan<<<1, 1024>>>();
    k_scatter<<<(N_EDGES + 255) / 256, 256>>>(srcp, tgtp, et);

    dim3 gRel(ROW_TILES, R_REL);
    dim3 gWarp((N_NODES + 7) / 8);
    int total4 = N_NODES * H_DIM / 4;

    // layer 1
    k_split_act<<<(total4 + 255) / 256, 256>>>(x, 0, total4);
    k_split_W<<<(R_REL * H_DIM * H_DIM + 255) / 256, 256>>>(W1);
    k_hgemm<<<gRel, 256>>>();
    k_wqk<<<4, 256>>>(W1, q1, k1);
    k_sqk<<<gWarp, 256>>>(x, 0);
    k_agg<<<gWarp, 256>>>(b1, 1);

    // layer 2
    k_split_act<<<(total4 + 255) / 256, 256>>>(nullptr, 1, total4);
    k_split_W<<<(R_REL * H_DIM * H_DIM + 255) / 256, 256>>>(W2);
    k_hgemm<<<gRel, 256>>>();
    k_wqk<<<4, 256>>>(W2, q2, k2);
    k_sqk<<<gWarp, 256>>>(nullptr, 1);
    k_agg<<<gWarp, 256>>>(b2, 2);

    // final linear
    k_gemm<true, true><<<dim3(ROW_TILES, 1), 256>>>(nullptr, 2, Wl, out, 0, bl,
                                                    N_NODES, 0L, 0L);
}

// round 5
// speedup vs baseline: 1.6942x; 1.1013x over previous
#include <cuda_runtime.h>
#include <cuda_bf16.h>
#include <cstdint>

#define N_NODES 50000
#define N_EDGES 800000
#define R_REL 8
#define H_DIM 128
#define ROW_TILES ((N_NODES + 127) / 128)
#define SCAN_BLKS ((N_NODES + 255) / 256)
#define PAD 136
#define TILE_E (128 * PAD)

// ---------------- scratch (device globals: allocation-free) ----------------
__device__ float g_xW[(size_t)R_REL * N_NODES * H_DIM];   // 204.8 MB
__device__ float g_h2[(size_t)N_NODES * H_DIM];
__device__ float g_sq[R_REL * N_NODES];
__device__ float g_sk[R_REL * N_NODES];
__device__ float g_sq2[R_REL * N_NODES];
__device__ float g_sk2[R_REL * N_NODES];
__device__ float g_wq[R_REL * H_DIM];
__device__ float g_wk[R_REL * H_DIM];
__device__ float g_wq2[R_REL * H_DIM];
__device__ float g_wk2[R_REL * H_DIM];
__device__ int   g_cnt[N_NODES];
__device__ int   g_rowptr[N_NODES + 1];
__device__ int   g_cursor[N_NODES];
__device__ int   g_csr[N_EDGES];
__device__ int   g_blksum[SCAN_BLKS];
__device__ int   g_total;
// split-bf16 operands for tensor-core GEMM
__device__ __nv_bfloat16 g_ahi[(size_t)N_NODES * H_DIM];
__device__ __nv_bfloat16 g_alo[(size_t)N_NODES * H_DIM];
__device__ __nv_bfloat16 g_bhi[R_REL * H_DIM * H_DIM];    // [r][n][k] = W[r][k][n]
__device__ __nv_bfloat16 g_blo[R_REL * H_DIM * H_DIM];

__device__ __forceinline__ uint32_t smem_u32(const void* p) {
    uint32_t a;
    asm("{ .reg .u64 t; cvta.to.shared.u64 t, %1; cvt.u32.u64 %0, t; }" : "=r"(a) : "l"(p));
    return a;
}

// ---------------- CSR build ----------------
__global__ void k_zero_cnt() {
    int i = blockIdx.x * blockDim.x + threadIdx.x;
    if (i < N_NODES) g_cnt[i] = 0;
}
__global__ void k_hist(const int* __restrict__ tgt) {
    int e = blockIdx.x * blockDim.x + threadIdx.x;
    if (e < N_EDGES) atomicAdd(&g_cnt[tgt[e]], 1);
}
__global__ __launch_bounds__(256) void k_scan_blk() {
    __shared__ int sm[256];
    int tid = threadIdx.x;
    int i = blockIdx.x * 256 + tid;
    int v = (i < N_NODES) ? g_cnt[i] : 0;
    sm[tid] = v;
    __syncthreads();
#pragma unroll
    for (int off = 1; off < 256; off <<= 1) {
        int t = (tid >= off) ? sm[tid - off] : 0;
        __syncthreads();
        sm[tid] += t;
        __syncthreads();
    }
    if (i < N_NODES) g_rowptr[i] = sm[tid] - v;
    if (tid == 255) g_blksum[blockIdx.x] = sm[255];
}
__global__ __launch_bounds__(256) void k_scan_top() {
    __shared__ int sm[256];
    int tid = threadIdx.x;
    int v = (tid < SCAN_BLKS) ? g_blksum[tid] : 0;
    sm[tid] = v;
    __syncthreads();
#pragma unroll
    for (int off = 1; off < 256; off <<= 1) {
        int t = (tid >= off) ? sm[tid - off] : 0;
        __syncthreads();
        sm[tid] += t;
        __syncthreads();
    }
    if (tid < SCAN_BLKS) g_blksum[tid] = sm[tid] - v;
    if (tid == 255) g_total = sm[255];
}
__global__ __launch_bounds__(256) void k_scan_add() {
    int i = blockIdx.x * 256 + threadIdx.x;
    if (i < N_NODES) {
        int v = g_rowptr[i] + g_blksum[blockIdx.x];
        g_rowptr[i] = v;
        g_cursor[i] = v;
    }
    if (i == 0) g_rowptr[N_NODES] = g_total;
}
__global__ void k_scatter(const int* __restrict__ src, const int* __restrict__ tgt,
                          const int* __restrict__ et) {
    int e = blockIdx.x * blockDim.x + threadIdx.x;
    if (e < N_EDGES) {
        int pos = atomicAdd(&g_cursor[tgt[e]], 1);
        g_csr[pos] = (et[e] << 17) | src[e];
    }
}

// ---------------- bf16 hi/lo splits ----------------
__global__ void k_split_act(const float* __restrict__ act, int total4) {
    int i = blockIdx.x * blockDim.x + threadIdx.x;
    if (i >= total4) return;
    float4 v = *(const float4*)&act[i * 4];
    __nv_bfloat16 h0 = __float2bfloat16(v.x), h1 = __float2bfloat16(v.y);
    __nv_bfloat16 h2 = __float2bfloat16(v.z), h3 = __float2bfloat16(v.w);
    __nv_bfloat162* ph = (__nv_bfloat162*)&g_ahi[i * 4];
    __nv_bfloat162* pl = (__nv_bfloat162*)&g_alo[i * 4];
    ph[0] = __nv_bfloat162(h0, h1);
    ph[1] = __nv_bfloat162(h2, h3);
    pl[0] = __nv_bfloat162(__float2bfloat16(v.x - __bfloat162float(h0)),
                           __float2bfloat16(v.y - __bfloat162float(h1)));
    pl[1] = __nv_bfloat162(__float2bfloat16(v.z - __bfloat162float(h2)),
                           __float2bfloat16(v.w - __bfloat162float(h3)));
}
// B[r][n][k] = W[r][k][n], split hi/lo
__global__ void k_split_W(const float* __restrict__ W) {
    int i = blockIdx.x * blockDim.x + threadIdx.x;   // r*16384 + n*128 + k
    if (i >= R_REL * H_DIM * H_DIM) return;
    int k = i & 127, n = (i >> 7) & 127, r = i >> 14;
    float w = W[(size_t)r * 16384 + k * 128 + n];
    __nv_bfloat16 h = __float2bfloat16(w);
    g_bhi[i] = h;
    g_blo[i] = __float2bfloat16(w - __bfloat162float(h));
}

// ---------------- HMMA GEMM: g_xW[r] = act @ W[r]  (split-bf16, 3 terms) ----------------
// CTA 128x128, 8 warps (4x2), warp tile 32x64. All 4 operand tiles SMEM-resident.
extern __shared__ __nv_bfloat16 s_dyn[];
__global__ __launch_bounds__(256) void k_hgemm() {
    int tid = threadIdx.x;
    int wid = tid >> 5, lane = tid & 31;
    int wr = wid >> 1, wc = wid & 1;
    int r = blockIdx.y;
    int rowBase = blockIdx.x * 128;

    uint32_t sb0 = smem_u32(&s_dyn[0]);                // Ahi
    uint32_t sb1 = smem_u32(&s_dyn[TILE_E]);           // Alo
    uint32_t sb2 = smem_u32(&s_dyn[2 * TILE_E]);       // Bhi
    uint32_t sb3 = smem_u32(&s_dyn[3 * TILE_E]);       // Blo

    // ---- single cp.async load of all tiles ----
    {
        const __nv_bfloat16* g0 = g_ahi;
        const __nv_bfloat16* g1 = g_alo;
        const __nv_bfloat16* g2 = g_bhi + (size_t)r * 16384;
        const __nv_bfloat16* g3 = g_blo + (size_t)r * 16384;
#pragma unroll
        for (int t = 0; t < 32; t++) {
            int idx = t * 256 + tid;
            int chunk = idx & 15;
            int row = (idx >> 4) & 127;
            int tile = idx >> 11;
            uint32_t base = (tile == 0) ? sb0 : (tile == 1) ? sb1 : (tile == 2) ? sb2 : sb3;
            uint32_t dst = base + (row * PAD + chunk * 8) * 2;
            const __nv_bfloat16* src;
            int sz = 16;
            if (tile < 2) {
                int gr = rowBase + row;
                src = ((tile == 0) ? g0 : g1) + (size_t)gr * 128 + chunk * 8;
                if (gr >= N_NODES) sz = 0;
            } else {
                src = ((tile == 2) ? g2 : g3) + row * 128 + chunk * 8;
            }
            asm volatile("cp.async.cg.shared.global [%0], [%1], 16, %2;"
                         :: "r"(dst), "l"(src), "r"(sz));
        }
        asm volatile("cp.async.commit_group;");
        asm volatile("cp.async.wait_group 0;");
        __syncthreads();
    }

    float acc[2][8][4];
#pragma unroll
    for (int mi = 0; mi < 2; mi++)
#pragma unroll
        for (int ni = 0; ni < 8; ni++)
#pragma unroll
            for (int j = 0; j < 4; j++) acc[mi][ni][j] = 0.f;

    // ldmatrix lane-address components
    int m8  = lane >> 3;
    int arow = (m8 & 1) * 8 + (lane & 7);
    int acol = (m8 >> 1) * 8;
    int bnr  = (m8 >> 1) * 8 + (lane & 7);
    int bkc  = (m8 & 1) * 8;

#pragma unroll
    for (int ks = 0; ks < 8; ks++) {
        int kc = ks * 16;
        uint32_t ah[2][4], al[2][4];
#pragma unroll
        for (int mi = 0; mi < 2; mi++) {
            uint32_t off = ((wr * 32 + mi * 16 + arow) * PAD + kc + acol) * 2;
            asm volatile("ldmatrix.sync.aligned.m8n8.x4.shared.b16 {%0,%1,%2,%3}, [%4];"
                         : "=r"(ah[mi][0]), "=r"(ah[mi][1]), "=r"(ah[mi][2]), "=r"(ah[mi][3])
                         : "r"(sb0 + off));
            asm volatile("ldmatrix.sync.aligned.m8n8.x4.shared.b16 {%0,%1,%2,%3}, [%4];"
                         : "=r"(al[mi][0]), "=r"(al[mi][1]), "=r"(al[mi][2]), "=r"(al[mi][3])
                         : "r"(sb1 + off));
        }
        uint32_t bh[8][2], bl[8][2];
#pragma unroll
        for (int np = 0; np < 4; np++) {
            uint32_t off = ((wc * 64 + np * 16 + bnr) * PAD + kc + bkc) * 2;
            asm volatile("ldmatrix.sync.aligned.m8n8.x4.shared.b16 {%0,%1,%2,%3}, [%4];"
                         : "=r"(bh[np * 2][0]), "=r"(bh[np * 2][1]),
                           "=r"(bh[np * 2 + 1][0]), "=r"(bh[np * 2 + 1][1])
                         : "r"(sb2 + off));
            asm volatile("ldmatrix.sync.aligned.m8n8.x4.shared.b16 {%0,%1,%2,%3}, [%4];"
                         : "=r"(bl[np * 2][0]), "=r"(bl[np * 2][1]),
                           "=r"(bl[np * 2 + 1][0]), "=r"(bl[np * 2 + 1][1])
                         : "r"(sb3 + off));
        }
#pragma unroll
        for (int mi = 0; mi < 2; mi++)
#pragma unroll
            for (int ni = 0; ni < 8; ni++) {
                asm volatile(
                    "mma.sync.aligned.m16n8k16.row.col.f32.bf16.bf16.f32 "
                    "{%0,%1,%2,%3}, {%4,%5,%6,%7}, {%8,%9}, {%0,%1,%2,%3};"
                    : "+f"(acc[mi][ni][0]), "+f"(acc[mi][ni][1]),
                      "+f"(acc[mi][ni][2]), "+f"(acc[mi][ni][3])
                    : "r"(ah[mi][0]), "r"(ah[mi][1]), "r"(ah[mi][2]), "r"(ah[mi][3]),
                      "r"(bh[ni][0]), "r"(bh[ni][1]));
                asm volatile(
                    "mma.sync.aligned.m16n8k16.row.col.f32.bf16.bf16.f32 "
                    "{%0,%1,%2,%3}, {%4,%5,%6,%7}, {%8,%9}, {%0,%1,%2,%3};"
                    : "+f"(acc[mi][ni][0]), "+f"(acc[mi][ni][1]),
                      "+f"(acc[mi][ni][2]), "+f"(acc[mi][ni][3])
                    : "r"(ah[mi][0]), "r"(ah[mi][1]), "r"(ah[mi][2]), "r"(ah[mi][3]),
                      "r"(bl[ni][0]), "r"(bl[ni][1]));
                asm volatile(
                    "mma.sync.aligned.m16n8k16.row.col.f32.bf16.bf16.f32 "
                    "{%0,%1,%2,%3}, {%4,%5,%6,%7}, {%8,%9}, {%0,%1,%2,%3};"
                    : "+f"(acc[mi][ni][0]), "+f"(acc[mi][ni][1]),
                      "+f"(acc[mi][ni][2]), "+f"(acc[mi][ni][3])
                    : "r"(al[mi][0]), "r"(al[mi][1]), "r"(al[mi][2]), "r"(al[mi][3]),
                      "r"(bh[ni][0]), "r"(bh[ni][1]));
            }
    }

    // epilogue
    float* dst = g_xW + (size_t)r * N_NODES * 128;
    int lr = lane >> 2, lc = (lane & 3) * 2;
#pragma unroll
    for (int mi = 0; mi < 2; mi++) {
        int row0 = rowBase + wr * 32 + mi * 16 + lr;
#pragma unroll
        for (int ni = 0; ni < 8; ni++) {
            int col = wc * 64 + ni * 8 + lc;
            if (row0 < N_NODES)
                *(float2*)&dst[(size_t)row0 * 128 + col] =
                    make_float2(acc[mi][ni][0], acc[mi][ni][1]);
            if (row0 + 8 < N_NODES)
                *(float2*)&dst[(size_t)(row0 + 8) * 128 + col] =
                    make_float2(acc[mi][ni][2], acc[mi][ni][3]);
        }
    }
}

// ---------------- fold q/k into W ----------------
__global__ void k_wqk(const float* __restrict__ W, const float* __restrict__ q,
                      const float* __restrict__ kv, int which) {
    int idx = blockIdx.x * blockDim.x + threadIdx.x;
    if (idx >= R_REL * H_DIM) return;
    const float* w = W + (size_t)idx * H_DIM;
    float aq = 0.f, ak = 0.f;
#pragma unroll 4
    for (int h = 0; h < H_DIM; h++) { float wv = w[h]; aq += wv * q[h]; ak += wv * kv[h]; }
    if (which == 0) { g_wq[idx] = aq; g_wk[idx] = ak; }
    else            { g_wq2[idx] = aq; g_wk2[idx] = ak; }
}

// ---------------- s_q / s_k (layer 1 only; layer 2 fused into k_agg) ----------------
__global__ __launch_bounds__(256) void k_sqk(const float* __restrict__ act) {
    __shared__ float swq[R_REL * H_DIM], swk[R_REL * H_DIM];
    int tid = threadIdx.x;
    for (int i = tid; i < R_REL * H_DIM; i += blockDim.x) { swq[i] = g_wq[i]; swk[i] = g_wk[i]; }
    __syncthreads();
    int n = blockIdx.x * 8 + (tid >> 5);
    int lane = tid & 31;
    if (n >= N_NODES) return;
    float4 a = *(const float4*)&act[(size_t)n * H_DIM + lane * 4];
    float accq[R_REL], acck[R_REL];
#pragma unroll
    for (int r = 0; r < R_REL; r++) {
        float4 wq4 = *(const float4*)&swq[r * H_DIM + lane * 4];
        float4 wk4 = *(const float4*)&swk[r * H_DIM + lane * 4];
        accq[r] = a.x * wq4.x + a.y * wq4.y + a.z * wq4.z + a.w * wq4.w;
        acck[r] = a.x * wk4.x + a.y * wk4.y + a.z * wk4.z + a.w * wk4.w;
    }
#pragma unroll
    for (int off = 16; off > 0; off >>= 1)
#pragma unroll
        for (int r = 0; r < R_REL; r++) {
            accq[r] += __shfl_xor_sync(0xffffffffu, accq[r], off);
            acck[r] += __shfl_xor_sync(0xffffffffu, acck[r], off);
        }
    if (lane < R_REL)            g_sq[lane * N_NODES + n] = accq[lane];
    else if (lane < 2 * R_REL)   g_sk[(lane - R_REL) * N_NODES + n] = acck[lane - R_REL];
}

// ---------------- fp32 GEMM (final linear only) ----------------
__device__ __forceinline__ void ffma2(unsigned long long& d, unsigned long long a,
                                      unsigned long long b) {
    asm volatile("fma.rn.f32x2 %0, %1, %2, %0;" : "+l"(d) : "l"(a), "l"(b));
}
__device__ __forceinline__ unsigned long long bc2(float x) {
    unsigned long long r;
    unsigned int u = __float_as_uint(x);
    asm("mov.b64 %0, {%1, %1};" : "=l"(r) : "r"(u));
    return r;
}
__global__ __launch_bounds__(256) void k_gemm_lin(
    const float* __restrict__ B, float* __restrict__ C,
    const float* __restrict__ bias, int M)
{
    __shared__ float As[32][132];
    __shared__ float Bs[32][132];
    const float* A = g_h2;
    int tid = threadIdx.x;
    int tx = tid & 15, ty = tid >> 4;
    int rowBase = blockIdx.x * 128;

    unsigned long long acc2[4][8];
#pragma unroll
    for (int i = 0; i < 4; i++)
#pragma unroll
        for (int j = 0; j < 8; j++) acc2[i][j] = 0ull;

    for (int k0 = 0; k0 < 128; k0 += 32) {
#pragma unroll
        for (int it = 0; it < 4; it++) {
            int f = it * 256 + tid;
            int row = f >> 3, kq = f & 7;
            float4 v = make_float4(0.f, 0.f, 0.f, 0.f);
            if (rowBase + row < M)
                v = *(const float4*)&A[(size_t)(rowBase + row) * 128 + k0 + kq * 4];
            As[kq * 4 + 0][row] = v.x;
            As[kq * 4 + 1][row] = v.y;
            As[kq * 4 + 2][row] = v.z;
            As[kq * 4 + 3][row] = v.w;
        }
#pragma unroll
        for (int it = 0; it < 4; it++) {
            int f = it * 256 + tid;
            int col = f >> 3, kq = f & 7;
            float4 v = *(const float4*)&B[(size_t)col * 128 + k0 + kq * 4];
            Bs[kq * 4 + 0][col] = v.x;
            Bs[kq * 4 + 1][col] = v.y;
            Bs[kq * 4 + 2][col] = v.z;
            Bs[kq * 4 + 3][col] = v.w;
        }
        __syncthreads();
#pragma unroll 4
        for (int kk = 0; kk < 32; kk++) {
            const unsigned long long* ap = (const unsigned long long*)&As[kk][ty * 8];
            unsigned long long a0 = ap[0], a1 = ap[1], a2 = ap[2], a3 = ap[3];
            float4 bA = *(const float4*)&Bs[kk][tx * 8];
            float4 bB = *(const float4*)&Bs[kk][tx * 8 + 4];
            unsigned long long bb[8];
            bb[0] = bc2(bA.x); bb[1] = bc2(bA.y); bb[2] = bc2(bA.z); bb[3] = bc2(bA.w);
            bb[4] = bc2(bB.x); bb[5] = bc2(bB.y); bb[6] = bc2(bB.z); bb[7] = bc2(bB.w);
#pragma unroll
            for (int j = 0; j < 8; j++) {
                ffma2(acc2[0][j], a0, bb[j]);
                ffma2(acc2[1][j], a1, bb[j]);
                ffma2(acc2[2][j], a2, bb[j]);
                ffma2(acc2[3][j], a3, bb[j]);
            }
        }
        __syncthreads();
    }
#pragma unroll
    for (int i4 = 0; i4 < 4; i4++) {
        int row0 = rowBase + ty * 8 + 2 * i4;
#pragma unroll
        for (int half = 0; half < 2; half++) {
            int row = row0 + half;
            if (row >= M) continue;
            float o[8];
#pragma unroll
            for (int j = 0; j < 8; j++) {
                float2 p = *(float2*)&acc2[i4][j];
                o[j] = half ? p.y : p.x;
            }
#pragma unroll
            for (int j = 0; j < 8; j++) o[j] += bias[tx * 8 + j];
            *(float4*)&C[(size_t)row * 128 + tx * 8]     = make_float4(o[0], o[1], o[2], o[3]);
            *(float4*)&C[(size_t)row * 128 + tx * 8 + 4] = make_float4(o[4], o[5], o[6], o[7]);
        }
    }
}

// ---------------- softmax + aggregate (+ fused split & next-layer sqk) ----------------
template<bool FUSE, bool SRC2, bool STOREH2>
__global__ __launch_bounds__(256) void k_agg(const float* __restrict__ bias) {
    __shared__ float swq[R_REL * H_DIM], swk[R_REL * H_DIM];
    int tid = threadIdx.x;
    int lane = tid & 31;
    if (FUSE) {
        for (int i = tid; i < R_REL * H_DIM; i += 256) { swq[i] = g_wq2[i]; swk[i] = g_wk2[i]; }
        __syncthreads();
    }
    int n = blockIdx.x * 8 + (tid >> 5);
    if (n >= N_NODES) return;
    const float* SQ = SRC2 ? g_sq2 : g_sq;
    const float* SK = SRC2 ? g_sk2 : g_sk;
    int s = g_rowptr[n], e = g_rowptr[n + 1];

    float mx = -3.0e38f;
    for (int i = s + lane; i < e; i += 32) {
        int p = g_csr[i]; int sr = p & 0x1FFFF; int r = p >> 17;
        float v = SQ[r * N_NODES + n] + SK[r * N_NODES + sr];
        v = v > 0.f ? v : 0.2f * v;
        mx = fmaxf(mx, v);
    }
#pragma unroll
    for (int off = 16; off > 0; off >>= 1) mx = fmaxf(mx, __shfl_xor_sync(0xffffffffu, mx, off));

    float den = 0.f;
    for (int i = s + lane; i < e; i += 32) {
        int p = g_csr[i]; int sr = p & 0x1FFFF; int r = p >> 17;
        float v = SQ[r * N_NODES + n] + SK[r * N_NODES + sr];
        v = v > 0.f ? v : 0.2f * v;
        den += __expf(v - mx);
    }
#pragma unroll
    for (int off = 16; off > 0; off >>= 1) den += __shfl_xor_sync(0xffffffffu, den, off);
    float inv = 1.f / (den + 1e-16f);

    float4 acc = make_float4(0.f, 0.f, 0.f, 0.f);
    int i = s;
    for (; i + 1 < e; i += 2) {
        int p0 = g_csr[i], p1 = g_csr[i + 1];
        int s0 = p0 & 0x1FFFF, r0 = p0 >> 17;
        int s1 = p1 & 0x1FFFF, r1 = p1 >> 17;
        float v0 = SQ[r0 * N_NODES + n] + SK[r0 * N_NODES + s0];
        float v1 = SQ[r1 * N_NODES + n] + SK[r1 * N_NODES + s1];
        v0 = v0 > 0.f ? v0 : 0.2f * v0;
        v1 = v1 > 0.f ? v1 : 0.2f * v1;
        float w0 = __expf(v0 - mx) * inv;
        float w1 = __expf(v1 - mx) * inv;
        float4 ra = *(const float4*)&g_xW[((size_t)r0 * N_NODES + s0) * 128 + lane * 4];
        float4 rb = *(const float4*)&g_xW[((size_t)r1 * N_NODES + s1) * 128 + lane * 4];
        acc.x += w0 * ra.x + w1 * rb.x;
        acc.y += w0 * ra.y + w1 * rb.y;
        acc.z += w0 * ra.z + w1 * rb.z;
        acc.w += w0 * ra.w + w1 * rb.w;
    }
    if (i < e) {
        int p = g_csr[i]; int s0 = p & 0x1FFFF; int r = p >> 17;
        float v = SQ[r * N_NODES + n] + SK[r * N_NODES + s0];
        v = v > 0.f ? v : 0.2f * v;
        float w = __expf(v - mx) * inv;
        float4 ra = *(const float4*)&g_xW[((size_t)r * N_NODES + s0) * 128 + lane * 4];
        acc.x += w * ra.x; acc.y += w * ra.y; acc.z += w * ra.z; acc.w += w * ra.w;
    }
    float4 bv = *(const float4*)&bias[lane * 4];
    float4 o;
    o.x = fmaxf(acc.x + bv.x, 0.f);
    o.y = fmaxf(acc.y + bv.y, 0.f);
    o.z = fmaxf(acc.z + bv.z, 0.f);
    o.w = fmaxf(acc.w + bv.w, 0.f);

    if (STOREH2)
        *(float4*)&g_h2[(size_t)n * 128 + lane * 4] = o;

    if (FUSE) {
        // bf16 hi/lo split of h1 for the next GEMM
        size_t base = (size_t)n * 128 + lane * 4;
        __nv_bfloat16 h0 = __float2bfloat16(o.x), h1 = __float2bfloat16(o.y);
        __nv_bfloat16 h2b = __float2bfloat16(o.z), h3 = __float2bfloat16(o.w);
        __nv_bfloat162* ph = (__nv_bfloat162*)&g_ahi[base];
        __nv_bfloat162* pl = (__nv_bfloat162*)&g_alo[base];
        ph[0] = __nv_bfloat162(h0, h1);
        ph[1] = __nv_bfloat162(h2b, h3);
        pl[0] = __nv_bfloat162(__float2bfloat16(o.x - __bfloat162float(h0)),
                               __float2bfloat16(o.y - __bfloat162float(h1)));
        pl[1] = __nv_bfloat162(__float2bfloat16(o.z - __bfloat162float(h2b)),
                               __float2bfloat16(o.w - __bfloat162float(h3)));
        // next-layer s_q / s_k
        float accq[R_REL], acck[R_REL];
#pragma unroll
        for (int r = 0; r < R_REL; r++) {
            float4 wq4 = *(const float4*)&swq[r * H_DIM + lane * 4];
            float4 wk4 = *(const float4*)&swk[r * H_DIM + lane * 4];
            accq[r] = o.x * wq4.x + o.y * wq4.y + o.z * wq4.z + o.w * wq4.w;
            acck[r] = o.x * wk4.x + o.y * wk4.y + o.z * wk4.z + o.w * wk4.w;
        }
#pragma unroll
        for (int off = 16; off > 0; off >>= 1)
#pragma unroll
            for (int r = 0; r < R_REL; r++) {
                accq[r] += __shfl_xor_sync(0xffffffffu, accq[r], off);
                acck[r] += __shfl_xor_sync(0xffffffffu, acck[r], off);
            }
        if (lane < R_REL)            g_sq2[lane * N_NODES + n] = accq[lane];
        else if (lane < 2 * R_REL)   g_sk2[(lane - R_REL) * N_NODES + n] = acck[lane - R_REL];
    }
}

// ---------------- launch ----------------
extern "C" void kernel_launch(void* const* d_in, const int* in_sizes, int n_in,
                              void* d_out, int out_size) {
    const float* x  = (const float*)d_in[0];
    const int*   ei = (const int*)d_in[1];
    const int*   et = (const int*)d_in[2];
    const float* W1 = (const float*)d_in[4];
    const float* q1 = (const float*)d_in[5];
    const float* k1 = (const float*)d_in[6];
    const float* b1 = (const float*)d_in[7];
    const float* W2 = (const float*)d_in[8];
    const float* q2 = (const float*)d_in[9];
    const float* k2 = (const float*)d_in[10];
    const float* b2 = (const float*)d_in[11];
    const float* Wl = (const float*)d_in[12];
    const float* bl = (const float*)d_in[13];
    float* out = (float*)d_out;
    const int* srcp = ei;
    const int* tgtp = ei + N_EDGES;

    static bool attr_done = false;
    if (!attr_done) {
        cudaFuncSetAttribute(k_hgemm, cudaFuncAttributeMaxDynamicSharedMemorySize,
                             4 * TILE_E * 2);
        attr_done = true;
    }

    // CSR build
    k_zero_cnt<<<(N_NODES + 255) / 256, 256>>>();
    k_hist<<<(N_EDGES + 255) / 256, 256>>>(tgtp);
    k_scan_blk<<<SCAN_BLKS, 256>>>();
    k_scan_top<<<1, 256>>>();
    k_scan_add<<<SCAN_BLKS, 256>>>();
    k_scatter<<<(N_EDGES + 255) / 256, 256>>>(srcp, tgtp, et);

    dim3 gRel(ROW_TILES, R_REL);
    dim3 gWarp((N_NODES + 7) / 8);
    int total4 = N_NODES * H_DIM / 4;
    int smem = 4 * TILE_E * 2;

    // layer 1
    k_split_act<<<(total4 + 255) / 256, 256>>>(x, total4);
    k_split_W<<<(R_REL * H_DIM * H_DIM + 255) / 256, 256>>>(W1);
    k_hgemm<<<gRel, 256, smem>>>();
    k_wqk<<<4, 256>>>(W1, q1, k1, 0);
    k_sqk<<<gWarp, 256>>>(x);
    k_wqk<<<4, 256>>>(W2, q2, k2, 1);
    k_agg<true, false, false><<<gWarp, 256>>>(b1);   // writes ahi/alo + sq2/sk2

    // layer 2
    k_split_W<<<(R_REL * H_DIM * H_DIM + 255) / 256, 256>>>(W2);
    k_hgemm<<<gRel, 256, smem>>>();
    k_agg<false, true, true><<<gWarp, 256>>>(b2);    // writes g_h2

    // final linear
    k_gemm_lin<<<ROW_TILES, 256>>>(Wl, out, bl, N_NODES);
}

// round 6
// speedup vs baseline: 1.8712x; 1.1045x over previous
#include <cuda_runtime.h>
#include <cuda_bf16.h>
#include <cstdint>

#define N_NODES 50000
#define N_EDGES 800000
#define R_REL 8
#define H_DIM 128
#define ROW_TILES ((N_NODES + 127) / 128)
#define SCAN_BLKS ((N_NODES + 255) / 256)
#define PAD 136
#define TILE_E (128 * PAD)

// ---------------- scratch (device globals: allocation-free) ----------------
__device__ float g_xW[(size_t)R_REL * N_NODES * H_DIM];   // 204.8 MB
__device__ float g_sq[R_REL * N_NODES];
__device__ float g_sk[R_REL * N_NODES];
__device__ float g_sq2[R_REL * N_NODES];
__device__ float g_sk2[R_REL * N_NODES];
__device__ float g_wq[R_REL * H_DIM];
__device__ float g_wk[R_REL * H_DIM];
__device__ float g_wq2[R_REL * H_DIM];
__device__ float g_wk2[R_REL * H_DIM];
__device__ float g_logit[N_EDGES];
__device__ int   g_cnt[N_NODES];
__device__ int   g_rowptr[N_NODES + 1];
__device__ int   g_cursor[N_NODES];
__device__ int   g_csr[N_EDGES];
__device__ int   g_blksum[SCAN_BLKS];
__device__ int   g_total;
// split-bf16 operands for tensor-core GEMM
__device__ __nv_bfloat16 g_ahi[(size_t)N_NODES * H_DIM];
__device__ __nv_bfloat16 g_alo[(size_t)N_NODES * H_DIM];
__device__ __nv_bfloat16 g_bhi[R_REL * H_DIM * H_DIM];    // [r][n][k] = W[r][k][n]
__device__ __nv_bfloat16 g_blo[R_REL * H_DIM * H_DIM];

__device__ __forceinline__ uint32_t smem_u32(const void* p) {
    uint32_t a;
    asm("{ .reg .u64 t; cvta.to.shared.u64 t, %1; cvt.u32.u64 %0, t; }" : "=r"(a) : "l"(p));
    return a;
}

// ---------------- CSR build ----------------
__global__ void k_zero_cnt() {
    int i = blockIdx.x * blockDim.x + threadIdx.x;
    if (i < N_NODES) g_cnt[i] = 0;
}
__global__ void k_hist(const int* __restrict__ tgt) {
    int e = blockIdx.x * blockDim.x + threadIdx.x;
    if (e < N_EDGES) atomicAdd(&g_cnt[tgt[e]], 1);
}
__global__ __launch_bounds__(256) void k_scan_blk() {
    __shared__ int sm[256];
    int tid = threadIdx.x;
    int i = blockIdx.x * 256 + tid;
    int v = (i < N_NODES) ? g_cnt[i] : 0;
    sm[tid] = v;
    __syncthreads();
#pragma unroll
    for (int off = 1; off < 256; off <<= 1) {
        int t = (tid >= off) ? sm[tid - off] : 0;
        __syncthreads();
        sm[tid] += t;
        __syncthreads();
    }
    if (i < N_NODES) g_rowptr[i] = sm[tid] - v;
    if (tid == 255) g_blksum[blockIdx.x] = sm[255];
}
__global__ __launch_bounds__(256) void k_scan_top() {
    __shared__ int sm[256];
    int tid = threadIdx.x;
    int v = (tid < SCAN_BLKS) ? g_blksum[tid] : 0;
    sm[tid] = v;
    __syncthreads();
#pragma unroll
    for (int off = 1; off < 256; off <<= 1) {
        int t = (tid >= off) ? sm[tid - off] : 0;
        __syncthreads();
        sm[tid] += t;
        __syncthreads();
    }
    if (tid < SCAN_BLKS) g_blksum[tid] = sm[tid] - v;
    if (tid == 255) g_total = sm[255];
}
__global__ __launch_bounds__(256) void k_scan_add() {
    int i = blockIdx.x * 256 + threadIdx.x;
    if (i < N_NODES) {
        int v = g_rowptr[i] + g_blksum[blockIdx.x];
        g_rowptr[i] = v;
        g_cursor[i] = v;
    }
    if (i == 0) g_rowptr[N_NODES] = g_total;
}
__global__ void k_scatter(const int* __restrict__ src, const int* __restrict__ tgt,
                          const int* __restrict__ et) {
    int e = blockIdx.x * blockDim.x + threadIdx.x;
    if (e < N_EDGES) {
        int pos = atomicAdd(&g_cursor[tgt[e]], 1);
        g_csr[pos] = (et[e] << 17) | src[e];
    }
}

// ---------------- bf16 hi/lo splits ----------------
__global__ void k_split_act(const float* __restrict__ act, int total4) {
    int i = blockIdx.x * blockDim.x + threadIdx.x;
    if (i >= total4) return;
    float4 v = *(const float4*)&act[i * 4];
    __nv_bfloat16 h0 = __float2bfloat16(v.x), h1 = __float2bfloat16(v.y);
    __nv_bfloat16 h2 = __float2bfloat16(v.z), h3 = __float2bfloat16(v.w);
    __nv_bfloat162* ph = (__nv_bfloat162*)&g_ahi[i * 4];
    __nv_bfloat162* pl = (__nv_bfloat162*)&g_alo[i * 4];
    ph[0] = __nv_bfloat162(h0, h1);
    ph[1] = __nv_bfloat162(h2, h3);
    pl[0] = __nv_bfloat162(__float2bfloat16(v.x - __bfloat162float(h0)),
                           __float2bfloat16(v.y - __bfloat162float(h1)));
    pl[1] = __nv_bfloat162(__float2bfloat16(v.z - __bfloat162float(h2)),
                           __float2bfloat16(v.w - __bfloat162float(h3)));
}
// B[r][n][k] = W[r][k][n], split hi/lo
__global__ void k_split_W(const float* __restrict__ W) {
    int i = blockIdx.x * blockDim.x + threadIdx.x;   // r*16384 + n*128 + k
    if (i >= R_REL * H_DIM * H_DIM) return;
    int k = i & 127, n = (i >> 7) & 127, r = i >> 14;
    float w = W[(size_t)r * 16384 + k * 128 + n];
    __nv_bfloat16 h = __float2bfloat16(w);
    g_bhi[i] = h;
    g_blo[i] = __float2bfloat16(w - __bfloat162float(h));
}
// Wl is already [out][k] — split without transpose into slot 0
__global__ void k_split_Wl(const float* __restrict__ Wl) {
    int i = blockIdx.x * blockDim.x + threadIdx.x;
    if (i >= H_DIM * H_DIM) return;
    float w = Wl[i];
    __nv_bfloat16 h = __float2bfloat16(w);
    g_bhi[i] = h;
    g_blo[i] = __float2bfloat16(w - __bfloat162float(h));
}

// ---------------- HMMA GEMM (split-bf16, 3 terms), 2-stage cp.async pipeline --------
// CTA 128x128, 8 warps (4x2), warp tile 32x64.
extern __shared__ __nv_bfloat16 s_dyn[];
template<bool LIN>
__global__ __launch_bounds__(256) void k_hgemm(float* __restrict__ outp,
                                               const float* __restrict__ bias) {
    int tid = threadIdx.x;
    int wid = tid >> 5, lane = tid & 31;
    int wr = wid >> 1, wc = wid & 1;
    int r = LIN ? 0 : blockIdx.y;
    int rowBase = blockIdx.x * 128;

    uint32_t sb[4] = { smem_u32(&s_dyn[0]), smem_u32(&s_dyn[TILE_E]),
                       smem_u32(&s_dyn[2 * TILE_E]), smem_u32(&s_dyn[3 * TILE_E]) };
    const __nv_bfloat16* gt[4] = { g_ahi, g_alo,
                                   g_bhi + (size_t)r * 16384, g_blo + (size_t)r * 16384 };

    // two commit groups: k 0..63, then k 64..127
#pragma unroll
    for (int half = 0; half < 2; half++) {
#pragma unroll
        for (int t = 0; t < 16; t++) {
            int idx = t * 256 + tid;              // 0..4095
            int ch = (idx & 7) + half * 8;
            int row = (idx >> 3) & 127;
            int tile = idx >> 10;
            uint32_t dst = sb[tile] + (row * PAD + ch * 8) * 2;
            const __nv_bfloat16* src;
            int sz = 16;
            if (tile < 2) {
                int gr = rowBase + row;
                src = gt[tile] + (size_t)gr * 128 + ch * 8;
                if (gr >= N_NODES) sz = 0;        // zero-fill
            } else {
                src = gt[tile] + row * 128 + ch * 8;
            }
            asm volatile("cp.async.cg.shared.global [%0], [%1], 16, %2;"
                         :: "r"(dst), "l"(src), "r"(sz));
        }
        asm volatile("cp.async.commit_group;");
    }

    float acc[2][8][4];
#pragma unroll
    for (int mi = 0; mi < 2; mi++)
#pragma unroll
        for (int ni = 0; ni < 8; ni++)
#pragma unroll
            for (int j = 0; j < 4; j++) acc[mi][ni][j] = 0.f;

    int m8  = lane >> 3;
    int arow = (m8 & 1) * 8 + (lane & 7);
    int acol = (m8 >> 1) * 8;
    int bnr  = (m8 >> 1) * 8 + (lane & 7);
    int bkc  = (m8 & 1) * 8;

#pragma unroll
    for (int half = 0; half < 2; half++) {
        if (half == 0) asm volatile("cp.async.wait_group 1;");
        else           asm volatile("cp.async.wait_group 0;");
        __syncthreads();
#pragma unroll
        for (int ks = half * 4; ks < half * 4 + 4; ks++) {
            int kc = ks * 16;
            uint32_t ah[2][4], al[2][4];
#pragma unroll
            for (int mi = 0; mi < 2; mi++) {
                uint32_t off = ((wr * 32 + mi * 16 + arow) * PAD + kc + acol) * 2;
                asm volatile("ldmatrix.sync.aligned.m8n8.x4.shared.b16 {%0,%1,%2,%3}, [%4];"
                             : "=r"(ah[mi][0]), "=r"(ah[mi][1]), "=r"(ah[mi][2]), "=r"(ah[mi][3])
                             : "r"(sb[0] + off));
                asm volatile("ldmatrix.sync.aligned.m8n8.x4.shared.b16 {%0,%1,%2,%3}, [%4];"
                             : "=r"(al[mi][0]), "=r"(al[mi][1]), "=r"(al[mi][2]), "=r"(al[mi][3])
                             : "r"(sb[1] + off));
            }
            uint32_t bh[8][2], bl[8][2];
#pragma unroll
            for (int np = 0; np < 4; np++) {
                uint32_t off = ((wc * 64 + np * 16 + bnr) * PAD + kc + bkc) * 2;
                asm volatile("ldmatrix.sync.aligned.m8n8.x4.shared.b16 {%0,%1,%2,%3}, [%4];"
                             : "=r"(bh[np * 2][0]), "=r"(bh[np * 2][1]),
                               "=r"(bh[np * 2 + 1][0]), "=r"(bh[np * 2 + 1][1])
                             : "r"(sb[2] + off));
                asm volatile("ldmatrix.sync.aligned.m8n8.x4.shared.b16 {%0,%1,%2,%3}, [%4];"
                             : "=r"(bl[np * 2][0]), "=r"(bl[np * 2][1]),
                               "=r"(bl[np * 2 + 1][0]), "=r"(bl[np * 2 + 1][1])
                             : "r"(sb[3] + off));
            }
#pragma unroll
            for (int mi = 0; mi < 2; mi++)
#pragma unroll
                for (int ni = 0; ni < 8; ni++) {
                    asm volatile(
                        "mma.sync.aligned.m16n8k16.row.col.f32.bf16.bf16.f32 "
                        "{%0,%1,%2,%3}, {%4,%5,%6,%7}, {%8,%9}, {%0,%1,%2,%3};"
                        : "+f"(acc[mi][ni][0]), "+f"(acc[mi][ni][1]),
                          "+f"(acc[mi][ni][2]), "+f"(acc[mi][ni][3])
                        : "r"(ah[mi][0]), "r"(ah[mi][1]), "r"(ah[mi][2]), "r"(ah[mi][3]),
                          "r"(bh[ni][0]), "r"(bh[ni][1]));
                    asm volatile(
                        "mma.sync.aligned.m16n8k16.row.col.f32.bf16.bf16.f32 "
                        "{%0,%1,%2,%3}, {%4,%5,%6,%7}, {%8,%9}, {%0,%1,%2,%3};"
                        : "+f"(acc[mi][ni][0]), "+f"(acc[mi][ni][1]),
                          "+f"(acc[mi][ni][2]), "+f"(acc[mi][ni][3])
                        : "r"(ah[mi][0]), "r"(ah[mi][1]), "r"(ah[mi][2]), "r"(ah[mi][3]),
                          "r"(bl[ni][0]), "r"(bl[ni][1]));
                    asm volatile(
                        "mma.sync.aligned.m16n8k16.row.col.f32.bf16.bf16.f32 "
                        "{%0,%1,%2,%3}, {%4,%5,%6,%7}, {%8,%9}, {%0,%1,%2,%3};"
                        : "+f"(acc[mi][ni][0]), "+f"(acc[mi][ni][1]),
                          "+f"(acc[mi][ni][2]), "+f"(acc[mi][ni][3])
                        : "r"(al[mi][0]), "r"(al[mi][1]), "r"(al[mi][2]), "r"(al[mi][3]),
                          "r"(bh[ni][0]), "r"(bh[ni][1]));
                }
        }
    }

    // epilogue
    float* dst = LIN ? outp : (g_xW + (size_t)r * N_NODES * 128);
    int lr = lane >> 2, lc = (lane & 3) * 2;
#pragma unroll
    for (int mi = 0; mi < 2; mi++) {
        int row0 = rowBase + wr * 32 + mi * 16 + lr;
#pragma unroll
        for (int ni = 0; ni < 8; ni++) {
            int col = wc * 64 + ni * 8 + lc;
            float b0 = 0.f, b1 = 0.f;
            if (LIN) { b0 = bias[col]; b1 = bias[col + 1]; }
            if (row0 < N_NODES)
                *(float2*)&dst[(size_t)row0 * 128 + col] =
                    make_float2(acc[mi][ni][0] + b0, acc[mi][ni][1] + b1);
            if (row0 + 8 < N_NODES)
                *(float2*)&dst[(size_t)(row0 + 8) * 128 + col] =
                    make_float2(acc[mi][ni][2] + b0, acc[mi][ni][3] + b1);
        }
    }
}

// ---------------- fold q/k into W ----------------
__global__ void k_wqk(const float* __restrict__ W, const float* __restrict__ q,
                      const float* __restrict__ kv, int which) {
    int idx = blockIdx.x * blockDim.x + threadIdx.x;
    if (idx >= R_REL * H_DIM) return;
    const float* w = W + (size_t)idx * H_DIM;
    float aq = 0.f, ak = 0.f;
#pragma unroll 4
    for (int h = 0; h < H_DIM; h++) { float wv = w[h]; aq += wv * q[h]; ak += wv * kv[h]; }
    if (which == 0) { g_wq[idx] = aq; g_wk[idx] = ak; }
    else            { g_wq2[idx] = aq; g_wk2[idx] = ak; }
}

// ---------------- s_q / s_k (layer 1 only) ----------------
__global__ __launch_bounds__(256) void k_sqk(const float* __restrict__ act) {
    __shared__ float swq[R_REL * H_DIM], swk[R_REL * H_DIM];
    int tid = threadIdx.x;
    for (int i = tid; i < R_REL * H_DIM; i += blockDim.x) { swq[i] = g_wq[i]; swk[i] = g_wk[i]; }
    __syncthreads();
    int n = blockIdx.x * 8 + (tid >> 5);
    int lane = tid & 31;
    if (n >= N_NODES) return;
    float4 a = *(const float4*)&act[(size_t)n * H_DIM + lane * 4];
    float accq[R_REL], acck[R_REL];
#pragma unroll
    for (int r = 0; r < R_REL; r++) {
        float4 wq4 = *(const float4*)&swq[r * H_DIM + lane * 4];
        float4 wk4 = *(const float4*)&swk[r * H_DIM + lane * 4];
        accq[r] = a.x * wq4.x + a.y * wq4.y + a.z * wq4.z + a.w * wq4.w;
        acck[r] = a.x * wk4.x + a.y * wk4.y + a.z * wk4.z + a.w * wk4.w;
    }
#pragma unroll
    for (int off = 16; off > 0; off >>= 1)
#pragma unroll
        for (int r = 0; r < R_REL; r++) {
            accq[r] += __shfl_xor_sync(0xffffffffu, accq[r], off);
            acck[r] += __shfl_xor_sync(0xffffffffu, acck[r], off);
        }
    if (lane < R_REL)            g_sq[lane * N_NODES + n] = accq[lane];
    else if (lane < 2 * R_REL)   g_sk[(lane - R_REL) * N_NODES + n] = acck[lane - R_REL];
}

// ---------------- softmax + aggregate: online softmax + cached logits ----------------
// FUSE: also emit next-layer sq2/sk2 + bf16 splits.  SPLIT: emit bf16 splits only.
template<bool FUSE, bool SRC2, bool SPLIT>
__global__ __launch_bounds__(256) void k_agg(const float* __restrict__ bias) {
    __shared__ float swq[R_REL * H_DIM], swk[R_REL * H_DIM];
    int tid = threadIdx.x;
    int lane = tid & 31;
    if (FUSE) {
        for (int i = tid; i < R_REL * H_DIM; i += 256) { swq[i] = g_wq2[i]; swk[i] = g_wk2[i]; }
        __syncthreads();
    }
    int n = blockIdx.x * 8 + (tid >> 5);
    if (n >= N_NODES) return;
    const float* SQ = SRC2 ? g_sq2 : g_sq;
    const float* SK = SRC2 ? g_sk2 : g_sk;
    int s = g_rowptr[n], e = g_rowptr[n + 1];

    // pass 1: compute + cache logits, online (max, denom)
    float mx = -3.0e38f, den = 0.f;
    for (int i = s + lane; i < e; i += 32) {
        int p = g_csr[i]; int sr = p & 0x1FFFF; int r = p >> 17;
        float v = SQ[r * N_NODES + n] + SK[r * N_NODES + sr];
        v = v > 0.f ? v : 0.2f * v;
        g_logit[i] = v;
        float nm = fmaxf(mx, v);
        den = den * __expf(mx - nm) + __expf(v - nm);
        mx = nm;
    }
#pragma unroll
    for (int off = 16; off > 0; off >>= 1) {
        float m2 = __shfl_xor_sync(0xffffffffu, mx, off);
        float d2 = __shfl_xor_sync(0xffffffffu, den, off);
        float nm = fmaxf(mx, m2);
        den = den * __expf(mx - nm) + d2 * __expf(m2 - nm);
        mx = nm;
    }
    float inv = 1.f / (den + 1e-16f);

    // pass 2: weighted gather (sequential logit reads)
    float4 acc = make_float4(0.f, 0.f, 0.f, 0.f);
    int i = s;
    for (; i + 1 < e; i += 2) {
        int p0 = g_csr[i], p1 = g_csr[i + 1];
        int s0 = p0 & 0x1FFFF, r0 = p0 >> 17;
        int s1 = p1 & 0x1FFFF, r1 = p1 >> 17;
        float w0 = __expf(g_logit[i] - mx) * inv;
        float w1 = __expf(g_logit[i + 1] - mx) * inv;
        float4 ra = *(const float4*)&g_xW[((size_t)r0 * N_NODES + s0) * 128 + lane * 4];
        float4 rb = *(const float4*)&g_xW[((size_t)r1 * N_NODES + s1) * 128 + lane * 4];
        acc.x += w0 * ra.x + w1 * rb.x;
        acc.y += w0 * ra.y + w1 * rb.y;
        acc.z += w0 * ra.z + w1 * rb.z;
        acc.w += w0 * ra.w + w1 * rb.w;
    }
    if (i < e) {
        int p = g_csr[i]; int s0 = p & 0x1FFFF; int r = p >> 17;
        float w = __expf(g_logit[i] - mx) * inv;
        float4 ra = *(const float4*)&g_xW[((size_t)r * N_NODES + s0) * 128 + lane * 4];
        acc.x += w * ra.x; acc.y += w * ra.y; acc.z += w * ra.z; acc.w += w * ra.w;
    }
    float4 bv = *(const float4*)&bias[lane * 4];
    float4 o;
    o.x = fmaxf(acc.x + bv.x, 0.f);
    o.y = fmaxf(acc.y + bv.y, 0.f);
    o.z = fmaxf(acc.z + bv.z, 0.f);
    o.w = fmaxf(acc.w + bv.w, 0.f);

    if (FUSE || SPLIT) {
        size_t base = (size_t)n * 128 + lane * 4;
        __nv_bfloat16 h0 = __float2bfloat16(o.x), h1 = __float2bfloat16(o.y);
        __nv_bfloat16 h2b = __float2bfloat16(o.z), h3 = __float2bfloat16(o.w);
        __nv_bfloat162* ph = (__nv_bfloat162*)&g_ahi[base];
        __nv_bfloat162* pl = (__nv_bfloat162*)&g_alo[base];
        ph[0] = __nv_bfloat162(h0, h1);
        ph[1] = __nv_bfloat162(h2b, h3);
        pl[0] = __nv_bfloat162(__float2bfloat16(o.x - __bfloat162float(h0)),
                               __float2bfloat16(o.y - __bfloat162float(h1)));
        pl[1] = __nv_bfloat162(__float2bfloat16(o.z - __bfloat162float(h2b)),
                               __float2bfloat16(o.w - __bfloat162float(h3)));
    }
    if (FUSE) {
        float accq[R_REL], acck[R_REL];
#pragma unroll
        for (int r = 0; r < R_REL; r++) {
            float4 wq4 = *(const float4*)&swq[r * H_DIM + lane * 4];
            float4 wk4 = *(const float4*)&swk[r * H_DIM + lane * 4];
            accq[r] = o.x * wq4.x + o.y * wq4.y + o.z * wq4.z + o.w * wq4.w;
            acck[r] = o.x * wk4.x + o.y * wk4.y + o.z * wk4.z + o.w * wk4.w;
        }
#pragma unroll
        for (int off = 16; off > 0; off >>= 1)
#pragma unroll
            for (int r = 0; r < R_REL; r++) {
                accq[r] += __shfl_xor_sync(0xffffffffu, accq[r], off);
                acck[r] += __shfl_xor_sync(0xffffffffu, acck[r], off);
            }
        if (lane < R_REL)            g_sq2[lane * N_NODES + n] = accq[lane];
        else if (lane < 2 * R_REL)   g_sk2[(lane - R_REL) * N_NODES + n] = acck[lane - R_REL];
    }
}

// ---------------- launch ----------------
extern "C" void kernel_launch(void* const* d_in, const int* in_sizes, int n_in,
                              void* d_out, int out_size) {
    const float* x  = (const float*)d_in[0];
    const int*   ei = (const int*)d_in[1];
    const int*   et = (const int*)d_in[2];
    const float* W1 = (const float*)d_in[4];
    const float* q1 = (const float*)d_in[5];
    const float* k1 = (const float*)d_in[6];
    const float* b1 = (const float*)d_in[7];
    const float* W2 = (const float*)d_in[8];
    const float* q2 = (const float*)d_in[9];
    const float* k2 = (const float*)d_in[10];
    const float* b2 = (const float*)d_in[11];
    const float* Wl = (const float*)d_in[12];
    const float* bl = (const float*)d_in[13];
    float* out = (float*)d_out;
    const int* srcp = ei;
    const int* tgtp = ei + N_EDGES;

    static bool attr_done = false;
    if (!attr_done) {
        cudaFuncSetAttribute(k_hgemm<false>, cudaFuncAttributeMaxDynamicSharedMemorySize,
                             4 * TILE_E * 2);
        cudaFuncSetAttribute(k_hgemm<true>, cudaFuncAttributeMaxDynamicSharedMemorySize,
                             4 * TILE_E * 2);
        attr_done = true;
    }

    dim3 gRel(ROW_TILES, R_REL);
    dim3 gWarp((N_NODES + 7) / 8);
    int total4 = N_NODES * H_DIM / 4;
    int smem = 4 * TILE_E * 2;

    // ordered so launch #4 (ncu capture slot) is the layer-1 HMMA GEMM
    k_zero_cnt<<<(N_NODES + 255) / 256, 256>>>();
    k_split_act<<<(total4 + 255) / 256, 256>>>(x, total4);
    k_split_W<<<(R_REL * H_DIM * H_DIM + 255) / 256, 256>>>(W1);
    k_hgemm<false><<<gRel, 256, smem>>>(nullptr, nullptr);           // #4

    // CSR build
    k_hist<<<(N_EDGES + 255) / 256, 256>>>(tgtp);
    k_scan_blk<<<SCAN_BLKS, 256>>>();
    k_scan_top<<<1, 256>>>();
    k_scan_add<<<SCAN_BLKS, 256>>>();
    k_scatter<<<(N_EDGES + 255) / 256, 256>>>(srcp, tgtp, et);

    // layer-1 attention inputs
    k_wqk<<<4, 256>>>(W1, q1, k1, 0);
    k_sqk<<<gWarp, 256>>>(x);
    k_wqk<<<4, 256>>>(W2, q2, k2, 1);
    k_agg<true, false, false><<<gWarp, 256>>>(b1);   // h1 -> splits + sq2/sk2

    // layer 2
    k_split_W<<<(R_REL * H_DIM * H_DIM + 255) / 256, 256>>>(W2);
    k_hgemm<false><<<gRel, 256, smem>>>(nullptr, nullptr);
    k_agg<false, true, true><<<gWarp, 256>>>(b2);    // h2 -> splits

    // final linear via HMMA
    k_split_Wl<<<(H_DIM * H_DIM + 255) / 256, 256>>>(Wl);
    k_hgemm<true><<<dim3(ROW_TILES, 1), 256, smem>>>(out, bl);
}